// round 14
// baseline (speedup 1.0000x reference)
#include <cuda_runtime.h>

// Shape fixed by setup_inputs: x [8, 8192, 512] fp32, weight [512] fp32.
#define BB 8
#define TT 8192
#define CC 512
#define EPSF 1e-5f

#define NBLK 148                 // persistent: 1 block per SM, single wave
#define THREADS 1024             // 32 warps; warp w owns frame w of each tile
#define FPB 32                   // frames per tile (64 KB)
#define NT (BB * TT / FPB)       // 2048 tiles
#define BPB (TT / FPB)           // 256 tiles per batch
#define NBUF 3                   // smem tile buffers (192 KB)
#define MAXIT ((NT + NBLK - 1) / NBLK)   // 14

// Double-buffered published aggregates: low 32b = value, high 32b = flag.
__device__ unsigned long long g_pubS1[2][NT];
__device__ unsigned long long g_pubD[2][NT];
__device__ int g_parity;
__device__ unsigned int g_done;

__device__ __forceinline__ void publish(unsigned long long* slot, float v) {
    *(volatile unsigned long long*)slot =
        (1ull << 32) | (unsigned long long)__float_as_uint(v);
}

// Warp-collective (warp 0): sum predecessor aggregates [0, kb), kb <= 255.
// Issue all 8 candidate loads first, then spin only on stragglers.
__device__ __forceinline__ float lookback(unsigned long long* base, int kb, int lane) {
    unsigned long long u[8];
#pragma unroll
    for (int k = 0; k < 8; k++) {
        const int idx = lane + k * 32;
        u[k] = (idx < kb) ? *(volatile unsigned long long*)&base[idx] : (1ull << 32);
    }
    float v = 0.f;
#pragma unroll
    for (int k = 0; k < 8; k++) {
        const int idx = lane + k * 32;
        if (idx < kb) {
            while (!(u[k] >> 32)) u[k] = *(volatile unsigned long long*)&base[idx];
            v += __uint_as_float((unsigned)u[k]);
        }
    }
#pragma unroll
    for (int o = 16; o > 0; o >>= 1) v += __shfl_xor_sync(0xffffffffu, v, o);
    return v;
}

__device__ __forceinline__ float warpscan(float v, int lane) {
#pragma unroll
    for (int o = 1; o < 32; o <<= 1) {
        float t = __shfl_up_sync(0xffffffffu, v, o);
        if (lane >= o) v += t;
    }
    return v;
}

__global__ void __launch_bounds__(THREADS, 1)
fused(const float* __restrict__ x, const float* __restrict__ w,
      float* __restrict__ out) {
    extern __shared__ float sX[];             // [NBUF][FPB*CC] = 192 KB
    __shared__ float sS1[NBUF][FPB], sQ[NBUF][FPB];
    __shared__ float sMean[FPB], sInv[FPB];

    const int p = *(volatile int*)&g_parity;
    const int bid = blockIdx.x;
    const int wid = threadIdx.x >> 5;         // 0..31 == frame within tile
    const int lane = threadIdx.x & 31;

    // Per-lane weight registers: frame layout is identical for every tile.
    const float4* w4 = reinterpret_cast<const float4*>(w);
    float4 wv[4];
#pragma unroll
    for (int k = 0; k < 4; k++) wv[k] = w4[lane + k * 32];

    for (int it = 0; it <= MAXIT; it++) {
        const int t = it * NBLK + bid;
        const bool have = (t < NT);

        // ---------------- step A: load + reduce tile t ---------------------
        if (have) {
            const int s = it % NBUF;
            // Clear other parity's slot for this tile (for the NEXT launch).
            if (threadIdx.x == 0) {
                *(volatile unsigned long long*)&g_pubS1[1 - p][t] = 0ull;
                *(volatile unsigned long long*)&g_pubD[1 - p][t] = 0ull;
            }
            const size_t frame0 = (size_t)t * FPB;
            const float4* px =
                reinterpret_cast<const float4*>(x + (frame0 + wid) * CC);
            float4* sx = reinterpret_cast<float4*>(sX + (s * FPB + wid) * CC);

            float4 a[4];
#pragma unroll
            for (int k = 0; k < 4; k++) a[k] = __ldcs(px + lane + k * 32);

            float sum = 0.f, q = 0.f;
#pragma unroll
            for (int k = 0; k < 4; k++) {
                sx[lane + k * 32] = a[k];
                sum += (a[k].x + a[k].y) + (a[k].z + a[k].w);
                q += a[k].x * a[k].x + a[k].y * a[k].y
                   + a[k].z * a[k].z + a[k].w * a[k].w;
            }
#pragma unroll
            for (int o = 16; o > 0; o >>= 1) {
                sum += __shfl_xor_sync(0xffffffffu, sum, o);
                q += __shfl_xor_sync(0xffffffffu, q, o);
            }
            if (lane == 0) { sS1[s][wid] = sum; sQ[s][wid] = q; }
            __syncthreads();
            if (wid == 0) {
                const float incl = warpscan(sS1[s][lane], lane);
                if (lane == 31) publish(&g_pubS1[p][t], incl);
            }
        }

        // ---------------- step B: stats + normalize tile from prev iter ----
        const int pt = (it - 1) * NBLK + bid;
        if (it > 0 && pt < NT) {
            const int s = (it - 1) % NBUF;
            if (wid == 0) {
                const int kb = pt % BPB;
                const int batch = pt / BPB;
                const float a = sS1[s][lane];
                const float q = sQ[s][lane];

                const float incl = warpscan(a, lane);
                const float exclB = lookback(&g_pubS1[p][batch * BPB], kb, lane);

                const int tf = kb * FPB + lane;
                const float cnt = (float)(tf + 1) * (float)CC;
                const float m = (exclB + incl) / cnt;

                const float D = q - 2.f * m * a + (float)CC * m * m;
                const float dincl = warpscan(D, lane);
                if (lane == 31) publish(&g_pubD[p][pt], dincl);
                const float dexclB = lookback(&g_pubD[p][batch * BPB], kb, lane);

                sMean[lane] = m;
                sInv[lane] = rsqrtf((dexclB + dincl) / cnt + EPSF);
            }
            __syncthreads();

            const float m = sMean[wid];
            const float iv = sInv[wid];
            const size_t frame0 = (size_t)pt * FPB;
            const float4* sx =
                reinterpret_cast<const float4*>(sX + (s * FPB + wid) * CC);
            float4* po = reinterpret_cast<float4*>(out + (frame0 + wid) * CC);
#pragma unroll
            for (int k = 0; k < 4; k++) {
                float4 v = sx[lane + k * 32];
                float4 r;
                r.x = (v.x - m) * iv * wv[k].x;
                r.y = (v.y - m) * iv * wv[k].y;
                r.z = (v.z - m) * iv * wv[k].z;
                r.w = (v.w - m) * iv * wv[k].w;
                __stcs(&po[lane + k * 32], r);
            }
            // Protect sMean/sInv (and buffer rotation) from the next iteration.
            __syncthreads();
        }
    }

    // ---------------- epilogue: last block flips parity --------------------
    if (threadIdx.x == 0) {
        __threadfence();
        unsigned int n = atomicAdd(&g_done, 1u);
        if (n == NBLK - 1) {
            g_done = 0;
            g_parity = p ^ 1;
        }
    }
}

extern "C" void kernel_launch(void* const* d_in, const int* in_sizes, int n_in,
                              void* d_out, int out_size) {
    const float* x = (const float*)d_in[0];
    const float* w = (const float*)d_in[1];
    float* out = (float*)d_out;

    const int smem = NBUF * FPB * CC * 4;   // 192 KB
    cudaFuncSetAttribute(fused, cudaFuncAttributeMaxDynamicSharedMemorySize, smem);
    fused<<<NBLK, THREADS, smem>>>(x, w, out);
}

// round 15
// speedup vs baseline: 1.0495x; 1.0495x over previous
#include <cuda_runtime.h>

// Shape fixed by setup_inputs: x [8, 8192, 512] fp32, weight [512] fp32.
#define BB 8
#define TT 8192
#define CC 512
#define EPSF 1e-5f

#define NBLK 296                 // persistent: 2 blocks per SM, single wave
#define THREADS 512              // 16 warps; warp w owns frame w of a tile
#define FPB 16                   // frames per tile (32 KB)
#define NT (BB * TT / FPB)       // 4096 tiles
#define BPB (TT / FPB)           // 512 tiles per batch
#define NBUF 3                   // smem tile buffers (96 KB)
#define MAXIT 14                 // ceil(NT / NBLK)
#define SMEM_BYTES (NBUF * FPB * CC * 4)

// Double-buffered published aggregates: low 32b = value, high 32b = flag.
__device__ unsigned long long g_pubS1[2][NT];
__device__ unsigned long long g_pubD[2][NT];
__device__ int g_parity;
__device__ unsigned int g_done;

__device__ __forceinline__ void publish(unsigned long long* slot, float v) {
    *(volatile unsigned long long*)slot =
        (1ull << 32) | (unsigned long long)__float_as_uint(v);
}

// Warp-collective: sum 8 candidate predecessor slots [k0*32 .. k0*32+255].
__device__ __forceinline__ float lookback8(unsigned long long* base, int kb,
                                           int lane, int k0) {
    unsigned long long u[8];
#pragma unroll
    for (int k = 0; k < 8; k++) {
        const int idx = lane + (k0 + k) * 32;
        u[k] = (idx < kb) ? *(volatile unsigned long long*)&base[idx] : (1ull << 32);
    }
    float v = 0.f;
#pragma unroll
    for (int k = 0; k < 8; k++) {
        const int idx = lane + (k0 + k) * 32;
        if (idx < kb) {
            while (!(u[k] >> 32)) u[k] = *(volatile unsigned long long*)&base[idx];
            v += __uint_as_float((unsigned)u[k]);
        }
    }
    return v;
}

// Full lookback over [0, kb), kb <= 511 (16 slots/lane in 2 batches).
__device__ __forceinline__ float lookback(unsigned long long* base, int kb, int lane) {
    float v = lookback8(base, kb, lane, 0);
    if (kb > 256) v += lookback8(base, kb, lane, 8);
#pragma unroll
    for (int o = 16; o > 0; o >>= 1) v += __shfl_xor_sync(0xffffffffu, v, o);
    return v;
}

__device__ __forceinline__ float warpscan(float v, int lane) {
#pragma unroll
    for (int o = 1; o < 32; o <<= 1) {
        float t = __shfl_up_sync(0xffffffffu, v, o);
        if (lane >= o) v += t;
    }
    return v;
}

__global__ void __launch_bounds__(THREADS, 2)
fused(const float* __restrict__ x, const float* __restrict__ w,
      float* __restrict__ out) {
    extern __shared__ float sX[];             // [NBUF][FPB*CC] = 96 KB
    __shared__ float sS1[NBUF][FPB], sQ[NBUF][FPB];
    __shared__ float sMean[FPB], sInv[FPB];

    const int p = *(volatile int*)&g_parity;
    const int bid = blockIdx.x;
    const int wid = threadIdx.x >> 5;         // 0..15 == frame within tile
    const int lane = threadIdx.x & 31;

    // Per-lane weight registers (frame layout identical for every tile).
    const float4* w4 = reinterpret_cast<const float4*>(w);
    float4 wv[4];
#pragma unroll
    for (int k = 0; k < 4; k++) wv[k] = w4[lane + k * 32];

    for (int it = 0; it <= MAXIT; it++) {
        const int t = it * NBLK + bid;

        // ---------------- step A: load + reduce tile t into buf it%NBUF ----
        if (t < NT) {
            const int s = it % NBUF;
            if (threadIdx.x == 0) {           // clear other parity for NEXT launch
                *(volatile unsigned long long*)&g_pubS1[1 - p][t] = 0ull;
                *(volatile unsigned long long*)&g_pubD[1 - p][t] = 0ull;
            }
            const size_t frame0 = (size_t)t * FPB;
            const float4* px =
                reinterpret_cast<const float4*>(x + (frame0 + wid) * CC);
            float4* sx = reinterpret_cast<float4*>(sX + (s * FPB + wid) * CC);

            float4 a[4];
#pragma unroll
            for (int k = 0; k < 4; k++) a[k] = __ldcs(px + lane + k * 32);

            float sum = 0.f, q = 0.f;
#pragma unroll
            for (int k = 0; k < 4; k++) {
                sx[lane + k * 32] = a[k];
                sum += (a[k].x + a[k].y) + (a[k].z + a[k].w);
                q += a[k].x * a[k].x + a[k].y * a[k].y
                   + a[k].z * a[k].z + a[k].w * a[k].w;
            }
#pragma unroll
            for (int o = 16; o > 0; o >>= 1) {
                sum += __shfl_xor_sync(0xffffffffu, sum, o);
                q += __shfl_xor_sync(0xffffffffu, q, o);
            }
            if (lane == 0) { sS1[s][wid] = sum; sQ[s][wid] = q; }
            __syncthreads();
            if (wid == 0) {
                const float a0 = (lane < FPB) ? sS1[s][lane] : 0.f;
                const float incl = warpscan(a0, lane);
                if (lane == 31) publish(&g_pubS1[p][t], incl);
            }
        }

        // ---------------- step B: stats + normalize tile from prev iter ----
        const int pt = (it - 1) * NBLK + bid;
        if (it > 0 && pt < NT) {
            const int s = (it - 1) % NBUF;
            if (wid == 0) {
                const int kb = pt % BPB;
                const int batch = pt / BPB;
                const float a = (lane < FPB) ? sS1[s][lane] : 0.f;
                const float q = (lane < FPB) ? sQ[s][lane] : 0.f;

                const float incl = warpscan(a, lane);
                const float exclB = lookback(&g_pubS1[p][batch * BPB], kb, lane);

                const int tf = kb * FPB + lane;
                const float cnt = (float)(tf + 1) * (float)CC;
                const float m = (exclB + incl) / cnt;

                const float D = (lane < FPB)
                    ? (q - 2.f * m * a + (float)CC * m * m) : 0.f;
                const float dincl = warpscan(D, lane);
                if (lane == 31) publish(&g_pubD[p][pt], dincl);
                const float dexclB = lookback(&g_pubD[p][batch * BPB], kb, lane);

                if (lane < FPB) {
                    sMean[lane] = m;
                    sInv[lane] = rsqrtf((dexclB + dincl) / cnt + EPSF);
                }
            }
            __syncthreads();

            const float m = sMean[wid];
            const float iv = sInv[wid];
            const size_t frame0 = (size_t)pt * FPB;
            const float4* sx =
                reinterpret_cast<const float4*>(sX + (s * FPB + wid) * CC);
            float4* po = reinterpret_cast<float4*>(out + (frame0 + wid) * CC);
#pragma unroll
            for (int k = 0; k < 4; k++) {
                float4 v = sx[lane + k * 32];
                float4 r;
                r.x = (v.x - m) * iv * wv[k].x;
                r.y = (v.y - m) * iv * wv[k].y;
                r.z = (v.z - m) * iv * wv[k].z;
                r.w = (v.w - m) * iv * wv[k].w;
                __stcs(&po[lane + k * 32], r);
            }
            __syncthreads();   // protect sMean/sInv + buffer reuse next iter
        }
    }

    // ---------------- epilogue: last block flips parity --------------------
    if (threadIdx.x == 0) {
        __threadfence();
        unsigned int n = atomicAdd(&g_done, 1u);
        if (n == NBLK - 1) {
            g_done = 0;
            g_parity = p ^ 1;
        }
    }
}

extern "C" void kernel_launch(void* const* d_in, const int* in_sizes, int n_in,
                              void* d_out, int out_size) {
    const float* x = (const float*)d_in[0];
    const float* w = (const float*)d_in[1];
    float* out = (float*)d_out;

    cudaFuncSetAttribute(fused, cudaFuncAttributeMaxDynamicSharedMemorySize,
                         SMEM_BYTES);
    fused<<<NBLK, THREADS, SMEM_BYTES>>>(x, w, out);
}

// round 17
// speedup vs baseline: 1.5244x; 1.4526x over previous
#include <cuda_runtime.h>

// Shape fixed by setup_inputs: x [8, 8192, 512] fp32, weight [512] fp32.
#define BB 8
#define TT 8192
#define CC 512
#define EPSF 1e-5f

#define THREADS 256              // 8 warps; 4 blocks/SM -> 512 blocks, 1 wave
#define FPB 64                   // frames per tile
#define BPB (TT / FPB)           // 128 tiles per batch
#define NT (BB * TT / FPB)       // 1024 tiles
#define NBLK (NT / 2)            // 512 blocks, tiles {bid, bid+512}
#define FPW (FPB / 8)            // 8 frames per warp per tile
#define STASHF 2                 // tile-A frames per warp held in smem
#define SMEM_BYTES (8 * STASHF * CC * 4)   // 32 KB

// Double-buffered published aggregates: low 32b = value, high 32b = flag.
__device__ unsigned long long g_pubS1[2][NT];
__device__ unsigned long long g_pubD[2][NT];
__device__ int g_parity;
__device__ unsigned int g_done;

__device__ __forceinline__ void publish(unsigned long long* slot, float v) {
    *(volatile unsigned long long*)slot =
        (1ull << 32) | (unsigned long long)__float_as_uint(v);
}

struct F8 { float v[8]; };

// 32-byte evict-last load (sm_103a needs v8.b32 for L2::evict_last).
__device__ __forceinline__ F8 ldg_keep8(const float* p) {
    unsigned r0, r1, r2, r3, r4, r5, r6, r7;
    asm volatile(
        "ld.global.L2::evict_last.v8.b32 {%0,%1,%2,%3,%4,%5,%6,%7}, [%8];"
        : "=r"(r0), "=r"(r1), "=r"(r2), "=r"(r3),
          "=r"(r4), "=r"(r5), "=r"(r6), "=r"(r7)
        : "l"(p));
    F8 f;
    f.v[0] = __uint_as_float(r0); f.v[1] = __uint_as_float(r1);
    f.v[2] = __uint_as_float(r2); f.v[3] = __uint_as_float(r3);
    f.v[4] = __uint_as_float(r4); f.v[5] = __uint_as_float(r5);
    f.v[6] = __uint_as_float(r6); f.v[7] = __uint_as_float(r7);
    return f;
}

__device__ __forceinline__ F8 ldcs8(const float* p) {
    const float4* q = reinterpret_cast<const float4*>(p);
    float4 a = __ldcs(q), b = __ldcs(q + 1);
    F8 f;
    f.v[0] = a.x; f.v[1] = a.y; f.v[2] = a.z; f.v[3] = a.w;
    f.v[4] = b.x; f.v[5] = b.y; f.v[6] = b.z; f.v[7] = b.w;
    return f;
}

__device__ __forceinline__ F8 ld8(const float* p) {
    const float4* q = reinterpret_cast<const float4*>(p);
    float4 a = q[0], b = q[1];
    F8 f;
    f.v[0] = a.x; f.v[1] = a.y; f.v[2] = a.z; f.v[3] = a.w;
    f.v[4] = b.x; f.v[5] = b.y; f.v[6] = b.z; f.v[7] = b.w;
    return f;
}

__device__ __forceinline__ void stcs8(float* p, const F8& f) {
    float4* q = reinterpret_cast<float4*>(p);
    __stcs(q, make_float4(f.v[0], f.v[1], f.v[2], f.v[3]));
    __stcs(q + 1, make_float4(f.v[4], f.v[5], f.v[6], f.v[7]));
}

__device__ __forceinline__ void sts8(float* p, const F8& f) {
    float4* q = reinterpret_cast<float4*>(p);
    q[0] = make_float4(f.v[0], f.v[1], f.v[2], f.v[3]);
    q[1] = make_float4(f.v[4], f.v[5], f.v[6], f.v[7]);
}

// Warp-collective: sum predecessor aggregates [0, kb), kb <= 127 (4 slots/lane).
__device__ __forceinline__ float lookback(unsigned long long* base, int kb, int lane) {
    float v = 0.f;
#pragma unroll
    for (int k = 0; k < 4; k++) {
        const int idx = lane + k * 32;
        if (idx < kb) {
            unsigned long long u;
            do {
                u = *(volatile unsigned long long*)&base[idx];
            } while (!(u >> 32));
            v += __uint_as_float((unsigned)u);
        }
    }
#pragma unroll
    for (int o = 16; o > 0; o >>= 1) v += __shfl_xor_sync(0xffffffffu, v, o);
    return v;
}

__device__ __forceinline__ float warpscan(float v, int lane) {
#pragma unroll
    for (int o = 1; o < 32; o <<= 1) {
        float t = __shfl_up_sync(0xffffffffu, v, o);
        if (lane >= o) v += t;
    }
    return v;
}

// Warp 0: publish a tile's S1 block-aggregate (2 frames/lane over 64).
__device__ __forceinline__ void scan_publish(int tile, int p, const float* sS1,
                                             int lane) {
    const float incl = warpscan(sS1[2 * lane] + sS1[2 * lane + 1], lane);
    if (lane == 31) publish(&g_pubS1[p][tile], incl);
}

// Warp 0: lookbacks + per-frame mean/inv for one tile.
__device__ __forceinline__ void stats(int tile, int p, int lane,
                                      const float* sS1, const float* sQ,
                                      float* sMean, float* sInv) {
    const int kb = tile % BPB;
    const int batch = tile / BPB;
    unsigned long long* baseS = &g_pubS1[p][batch * BPB];
    unsigned long long* baseD = &g_pubD[p][batch * BPB];

    const float a0 = sS1[2 * lane];
    const float a1 = sS1[2 * lane + 1];
    const float q0 = sQ[2 * lane];
    const float q1 = sQ[2 * lane + 1];

    const float pairsum = a0 + a1;
    const float incl = warpscan(pairsum, lane);
    const float exclL = incl - pairsum;

    const float exclB = lookback(baseS, kb, lane);

    const int t0 = kb * FPB + 2 * lane;
    const float c0 = (float)(t0 + 1) * (float)CC;
    const float c1 = (float)(t0 + 2) * (float)CC;
    const float m0 = (exclB + exclL + a0) / c0;
    const float m1 = (exclB + exclL + a0 + a1) / c1;

    const float D0 = q0 - 2.f * m0 * a0 + (float)CC * m0 * m0;
    const float D1 = q1 - 2.f * m1 * a1 + (float)CC * m1 * m1;
    const float dpair = D0 + D1;
    const float dincl = warpscan(dpair, lane);
    const float dexclL = dincl - dpair;
    if (lane == 31) publish(&g_pubD[p][tile], dincl);

    const float dexclB = lookback(baseD, kb, lane);

    sMean[2 * lane] = m0;
    sMean[2 * lane + 1] = m1;
    sInv[2 * lane] = rsqrtf((dexclB + dexclL + D0) / c0 + EPSF);
    sInv[2 * lane + 1] = rsqrtf((dexclB + dexclL + D0 + D1) / c1 + EPSF);
}

// Reduce one frame's two F8 halves into (sum, sumsq), warp-collective.
__device__ __forceinline__ void reduce_frame(const F8& a, const F8& b,
                                             float& s, float& q) {
    s = 0.f; q = 0.f;
#pragma unroll
    for (int k = 0; k < 8; k++) {
        s += a.v[k] + b.v[k];
        q += a.v[k] * a.v[k] + b.v[k] * b.v[k];
    }
#pragma unroll
    for (int o = 16; o > 0; o >>= 1) {
        s += __shfl_xor_sync(0xffffffffu, s, o);
        q += __shfl_xor_sync(0xffffffffu, q, o);
    }
}

// Normalize one frame (two F8 halves) and stream to out.
__device__ __forceinline__ void norm_frame(const F8& a, const F8& b,
                                           const F8& w0, const F8& w1,
                                           float m, float iv, float* po, int lane) {
    F8 r0, r1;
#pragma unroll
    for (int k = 0; k < 8; k++) {
        r0.v[k] = (a.v[k] - m) * iv * w0.v[k];
        r1.v[k] = (b.v[k] - m) * iv * w1.v[k];
    }
    stcs8(po + lane * 8, r0);
    stcs8(po + 256 + lane * 8, r1);
}

__global__ void __launch_bounds__(THREADS, 4)
fused(const float* __restrict__ x, const float* __restrict__ w,
      float* __restrict__ out) {
    extern __shared__ float sStash[];         // [8 warps][STASHF][CC] = 32 KB
    __shared__ float sS1[2][FPB], sQ[2][FPB], sMean[2][FPB], sInv[2][FPB];

    const int p = *(volatile int*)&g_parity;
    const int wid = threadIdx.x >> 5;
    const int lane = threadIdx.x & 31;
    const int tileA = blockIdx.x;
    const int tileB = blockIdx.x + NBLK;
    const size_t f0A = (size_t)tileA * FPB;
    const size_t f0B = (size_t)tileB * FPB;

    // Clear the other parity's slots for the NEXT launch.
    if (threadIdx.x == 0) {
        *(volatile unsigned long long*)&g_pubS1[1 - p][tileA] = 0ull;
        *(volatile unsigned long long*)&g_pubD[1 - p][tileA] = 0ull;
        *(volatile unsigned long long*)&g_pubS1[1 - p][tileB] = 0ull;
        *(volatile unsigned long long*)&g_pubD[1 - p][tileB] = 0ull;
    }

    // Per-lane weights in the lane*8 layout (two halves of a 512-float frame).
    const F8 wl0 = ld8(w + lane * 8);
    const F8 wl1 = ld8(w + 256 + lane * 8);

    // ---------------- Phase 1 (merged): reduce A and B, stash A's first 2 --
    float* stash = sStash + wid * STASHF * CC;
#pragma unroll
    for (int j = 0; j < FPW; j++) {
        const int f = wid * FPW + j;
        const float* pA = x + (f0A + f) * CC;
        const float* pB = x + (f0B + f) * CC;
        F8 a0 = ldg_keep8(pA + lane * 8);
        F8 a1 = ldg_keep8(pA + 256 + lane * 8);
        F8 b0 = ldg_keep8(pB + lane * 8);
        F8 b1 = ldg_keep8(pB + 256 + lane * 8);

        if (j < STASHF) {
            sts8(stash + j * CC + lane * 8, a0);
            sts8(stash + j * CC + 256 + lane * 8, a1);
        }

        float sA, qA, sB, qB;
        reduce_frame(a0, a1, sA, qA);
        reduce_frame(b0, b1, sB, qB);
        if (lane == 0) {
            sS1[0][f] = sA; sQ[0][f] = qA;
            sS1[1][f] = sB; sQ[1][f] = qB;
        }
    }
    __syncthreads();

    // ---------------- Phase 2: publish both, join A ------------------------
    if (wid == 0) {
        scan_publish(tileA, p, sS1[0], lane);
        scan_publish(tileB, p, sS1[1], lane);
        stats(tileA, p, lane, sS1[0], sQ[0], sMean[0], sInv[0]);
    }
    __syncthreads();

    // ---------------- Phase 3a: norm A while warp 0 joins B ----------------
    if (wid == 0) stats(tileB, p, lane, sS1[1], sQ[1], sMean[1], sInv[1]);
    {
        // Frames 0..STASHF-1 from smem stash.
#pragma unroll
        for (int j = 0; j < STASHF; j++) {
            const int f = wid * FPW + j;
            F8 a = ld8(stash + j * CC + lane * 8);
            F8 b = ld8(stash + j * CC + 256 + lane * 8);
            norm_frame(a, b, wl0, wl1, sMean[0][f], sInv[0][f],
                       out + (f0A + f) * CC, lane);
        }
        // Frames STASHF..7 from gmem (__ldcs), 2-frame batched.
#pragma unroll
        for (int j = STASHF; j < FPW; j += 2) {
            const int f = wid * FPW + j;
            const float* p0 = x + (f0A + f) * CC;
            const float* p1 = x + (f0A + f + 1) * CC;
            F8 a0 = ldcs8(p0 + lane * 8), a1 = ldcs8(p0 + 256 + lane * 8);
            F8 b0 = ldcs8(p1 + lane * 8), b1 = ldcs8(p1 + 256 + lane * 8);
            norm_frame(a0, a1, wl0, wl1, sMean[0][f], sInv[0][f],
                       out + (f0A + f) * CC, lane);
            norm_frame(b0, b1, wl0, wl1, sMean[0][f + 1], sInv[0][f + 1],
                       out + (f0A + f + 1) * CC, lane);
        }
    }
    __syncthreads();

    // ---------------- Phase 3b: norm B -------------------------------------
#pragma unroll
    for (int j = 0; j < FPW; j += 2) {
        const int f = wid * FPW + j;
        const float* p0 = x + (f0B + f) * CC;
        const float* p1 = x + (f0B + f + 1) * CC;
        F8 a0 = ldcs8(p0 + lane * 8), a1 = ldcs8(p0 + 256 + lane * 8);
        F8 b0 = ldcs8(p1 + lane * 8), b1 = ldcs8(p1 + 256 + lane * 8);
        norm_frame(a0, a1, wl0, wl1, sMean[1][f], sInv[1][f],
                   out + (f0B + f) * CC, lane);
        norm_frame(b0, b1, wl0, wl1, sMean[1][f + 1], sInv[1][f + 1],
                   out + (f0B + f + 1) * CC, lane);
    }

    // ---------------- Epilogue: last block flips parity --------------------
    __syncthreads();
    if (threadIdx.x == 0) {
        __threadfence();
        unsigned int n = atomicAdd(&g_done, 1u);
        if (n == NBLK - 1) {
            g_done = 0;
            g_parity = p ^ 1;
        }
    }
}

extern "C" void kernel_launch(void* const* d_in, const int* in_sizes, int n_in,
                              void* d_out, int out_size) {
    const float* x = (const float*)d_in[0];
    const float* w = (const float*)d_in[1];
    float* out = (float*)d_out;

    fused<<<NBLK, THREADS, SMEM_BYTES>>>(x, w, out);
}